// round 1
// baseline (speedup 1.0000x reference)
#include <cuda_runtime.h>

#define NN 10000
#define EE 100000

// ---------------- scratch (static device globals; no allocation) ----------------
__device__ float g_h[NN * 32];
__device__ float g_coord[NN * 3];
__device__ float g_k2[(size_t)EE * 128];
__device__ float g_W3h[(size_t)NN * 4096];
__device__ float g_acch[NN * 32];
__device__ float g_accc[NN * 3];
__device__ float g_invc[NN];
__device__ int   g_cntc[NN];
__device__ int   g_cntr[NN];
__device__ int   g_fill[NN];
__device__ int   g_cptr[NN + 1];
__device__ int   g_ebc[EE];

// ---------------- init: h = x@fc1 + b, coord copy, zero accumulators/counters ----
__global__ void k_prep(const float* __restrict__ x, const float* __restrict__ w,
                       const float* __restrict__ b, const float* __restrict__ ci) {
    int idx = blockIdx.x * blockDim.x + threadIdx.x;
    if (idx < NN * 32) {
        int n = idx >> 5, j = idx & 31;
        float s = b[j];
        s += x[n * 3 + 0] * w[j] + x[n * 3 + 1] * w[32 + j] + x[n * 3 + 2] * w[64 + j];
        g_h[idx] = s;
        g_acch[idx] = 0.f;
    }
    if (idx < NN * 3) { g_coord[idx] = ci[idx]; g_accc[idx] = 0.f; }
    if (idx < NN) { g_cntc[idx] = 0; g_cntr[idx] = 0; g_fill[idx] = 0; }
}

__global__ void k_hist(const int* __restrict__ ei) {
    int e = blockIdx.x * blockDim.x + threadIdx.x;
    if (e < EE) {
        atomicAdd(&g_cntr[ei[e]], 1);        // row = out-degree (seg_mean denominator)
        atomicAdd(&g_cntc[ei[EE + e]], 1);   // col = grouping key
    }
}

// single-block exclusive scan of g_cntc -> g_cptr (N=10000, 1024 threads x 10)
__global__ void k_scan() {
    __shared__ int ss[1024];
    int t = threadIdx.x;
    int base = t * 10;
    int loc[10];
    int s = 0;
#pragma unroll
    for (int i = 0; i < 10; i++) {
        int v = (base + i < NN) ? g_cntc[base + i] : 0;
        loc[i] = s; s += v;
    }
    ss[t] = s;
    __syncthreads();
    for (int off = 1; off < 1024; off <<= 1) {
        int v = (t >= off) ? ss[t - off] : 0;
        __syncthreads();
        ss[t] += v;
        __syncthreads();
    }
    int pre = (t > 0) ? ss[t - 1] : 0;
#pragma unroll
    for (int i = 0; i < 10; i++)
        if (base + i < NN) g_cptr[base + i] = pre + loc[i];
    if (t == 1023) g_cptr[NN] = ss[1023];
}

__global__ void k_invc() {
    int n = blockIdx.x * blockDim.x + threadIdx.x;
    if (n < NN) {
        int c = g_cntr[n];
        g_invc[n] = 1.f / (float)(c > 0 ? c : 1);
    }
}

__global__ void k_scatter(const int* __restrict__ ei) {
    int e = blockIdx.x * blockDim.x + threadIdx.x;
    if (e < EE) {
        int c = ei[EE + e];
        int p = g_cptr[c] + atomicAdd(&g_fill[c], 1);
        g_ebc[p] = e;
    }
}

// -------- edge MLP: kin=[attr,radial] -> relu(@W1+b1)[64] -> relu(@W2+b2)[128] ----
// 64 edges/block, 256 threads. Weights staged in smem; k2 GEMM micro-tiled.
__global__ __launch_bounds__(256) void k_edge_mlp(
    const int* __restrict__ ei, const float* __restrict__ attr,
    const float* __restrict__ W1, const float* __restrict__ B1,
    const float* __restrict__ W2, const float* __restrict__ B2) {
    __shared__ float s_kin[64][8];
    __shared__ float s_k1[64][64];
    __shared__ float s_w2[64 * 64];
    __shared__ float s_w1[7 * 64];
    __shared__ float s_b1[64];
    __shared__ float s_b2[128];
    int t = threadIdx.x;
    int e0 = blockIdx.x * 64;

    for (int i = t; i < 7 * 64; i += 256) s_w1[i] = W1[i];
    if (t < 64) s_b1[t] = B1[t];
    if (t >= 64 && t < 192) s_b2[t - 64] = B2[t - 64];

    if (t < 64) {
        int e = e0 + t;
        float rad = 0.f;
        if (e < EE) {
            int r = ei[e], c = ei[EE + e];
            float d0 = g_coord[r * 3 + 0] - g_coord[c * 3 + 0];
            float d1 = g_coord[r * 3 + 1] - g_coord[c * 3 + 1];
            float d2 = g_coord[r * 3 + 2] - g_coord[c * 3 + 2];
            rad = d0 * d0 + d1 * d1 + d2 * d2;
#pragma unroll
            for (int q = 0; q < 6; q++) s_kin[t][q] = attr[e * 6 + q];
        } else {
#pragma unroll
            for (int q = 0; q < 6; q++) s_kin[t][q] = 0.f;
        }
        s_kin[t][6] = rad;
        s_kin[t][7] = 0.f;
    }
    __syncthreads();

    // k1 tile [64 edges x 64 cols]
    for (int i = t; i < 64 * 64; i += 256) {
        int e = i >> 6, c = i & 63;
        float s = s_b1[c];
#pragma unroll
        for (int q = 0; q < 7; q++) s += s_kin[e][q] * s_w1[q * 64 + c];
        s_k1[e][c] = fmaxf(s, 0.f);
    }
    __syncthreads();

    int cx = t & 31, ey = t >> 5;  // 8 edges per thread (ey*8+i), 2 cols (cx, cx+32)
    for (int half = 0; half < 2; half++) {
        for (int i = t; i < 64 * 64; i += 256)
            s_w2[i] = W2[(i >> 6) * 128 + half * 64 + (i & 63)];
        __syncthreads();

        float acc0[8], acc1[8];
#pragma unroll
        for (int i = 0; i < 8; i++) {
            acc0[i] = s_b2[half * 64 + cx];
            acc1[i] = s_b2[half * 64 + cx + 32];
        }
#pragma unroll 16
        for (int k = 0; k < 64; k++) {
            float b0 = s_w2[k * 64 + cx];
            float b1v = s_w2[k * 64 + cx + 32];
#pragma unroll
            for (int i = 0; i < 8; i++) {
                float a = s_k1[ey * 8 + i][k];
                acc0[i] += a * b0;
                acc1[i] += a * b1v;
            }
        }
#pragma unroll
        for (int i = 0; i < 8; i++) {
            int e = e0 + ey * 8 + i;
            if (e < EE) {
                g_k2[(size_t)e * 128 + half * 64 + cx]      = fmaxf(acc0[i], 0.f);
                g_k2[(size_t)e * 128 + half * 64 + cx + 32] = fmaxf(acc1[i], 0.f);
            }
        }
        __syncthreads();
    }
}

// -------- W3h GEMM: W3h[n][o] = sum_j h[n][j] * ker_w3_flat[o*32+j]  (o = c*32+i)
// block tile 32 nodes x 128 outs, K=32. 256 threads, 4n x 4o micro-tile.
__global__ __launch_bounds__(256) void k_w3h(const float* __restrict__ W3) {
    __shared__ float s_h[32][33];
    __shared__ float s_b[128][33];
    int t = threadIdx.x;
    int o0 = blockIdx.x * 128;
    int n0 = blockIdx.y * 32;

    for (int i = t; i < 32 * 32; i += 256) {
        int n = i >> 5, j = i & 31;
        s_h[n][j] = (n0 + n < NN) ? g_h[(n0 + n) * 32 + j] : 0.f;
    }
    for (int i = t; i < 128 * 32; i += 256) {
        int r = i >> 5, k = i & 31;
        s_b[r][k] = W3[(size_t)(o0 + r) * 32 + k];
    }
    __syncthreads();

    int ox = t & 31, ny = t >> 5;  // nodes ny*4+i, outs ox+32*j
    float acc[4][4];
#pragma unroll
    for (int i = 0; i < 4; i++)
#pragma unroll
        for (int j = 0; j < 4; j++) acc[i][j] = 0.f;

#pragma unroll
    for (int k = 0; k < 32; k++) {
        float a[4], b[4];
#pragma unroll
        for (int i = 0; i < 4; i++) a[i] = s_h[ny * 4 + i][k];       // broadcast in warp
#pragma unroll
        for (int j = 0; j < 4; j++) b[j] = s_b[ox + 32 * j][k];      // conflict-free
#pragma unroll
        for (int i = 0; i < 4; i++)
#pragma unroll
            for (int j = 0; j < 4; j++) acc[i][j] += a[i] * b[j];
    }
#pragma unroll
    for (int i = 0; i < 4; i++) {
        int n = n0 + ny * 4 + i;
        if (n < NN) {
#pragma unroll
            for (int j = 0; j < 4; j++)
                g_W3h[(size_t)n * 4096 + o0 + ox + 32 * j] = acc[i][j];
        }
    }
}

// -------- contraction: warp per (col) node. W3h[n] in 128 regs/lane.
// m[e,i] = sum_c k2[e,c]*W3h[n,c,i] + Bh[n,i]; phi = relu(m@cm1+cb1)@cm2;
// atomic scatter into acc_h[row], acc_c[row].
__global__ __launch_bounds__(128) void k_contract(
    const int* __restrict__ ei, const float* __restrict__ B3,
    const float* __restrict__ CW1, const float* __restrict__ CB1,
    const float* __restrict__ CW2) {
    int lane = threadIdx.x & 31;
    int n = blockIdx.x * 4 + (threadIdx.x >> 5);
    if (n >= NN) return;
    int beg = g_cptr[n], end = g_cptr[n + 1];
    if (beg == end) return;

    float r[128];
    const float* wp = g_W3h + (size_t)n * 4096 + lane;
#pragma unroll
    for (int c = 0; c < 128; c++) r[c] = wp[c * 32];

    float hv = g_h[n * 32 + lane];
    float bh = 0.f;
#pragma unroll
    for (int j = 0; j < 32; j++)
        bh += B3[lane * 32 + j] * __shfl_sync(0xffffffffu, hv, j);

    float c0 = g_coord[n * 3 + 0], c1 = g_coord[n * 3 + 1], c2 = g_coord[n * 3 + 2];

    float cw1l[32];
#pragma unroll
    for (int i = 0; i < 32; i++) cw1l[i] = CW1[i * 32 + lane];
    float cb1l = CB1[lane];
    float cw2l = CW2[lane];

    for (int p = beg; p < end; p++) {
        int e = g_ebc[p];
        int rn = ei[e];
        float d0 = g_coord[rn * 3 + 0] - c0;
        float d1 = g_coord[rn * 3 + 1] - c1;
        float d2 = g_coord[rn * 3 + 2] - c2;

        float m = bh;
        const float4* kp = (const float4*)(g_k2 + (size_t)e * 128);
#pragma unroll
        for (int c = 0; c < 32; c++) {
            float4 kv = kp[c];  // uniform across warp; L2/DRAM streamed once
            m += kv.x * r[4 * c] + kv.y * r[4 * c + 1] + kv.z * r[4 * c + 2] + kv.w * r[4 * c + 3];
        }

        float tj = cb1l;
#pragma unroll
        for (int i = 0; i < 32; i++)
            tj += __shfl_sync(0xffffffffu, m, i) * cw1l[i];
        tj = fmaxf(tj, 0.f) * cw2l;
#pragma unroll
        for (int o = 16; o; o >>= 1) tj += __shfl_xor_sync(0xffffffffu, tj, o);
        // tj now = phi on all lanes

        atomicAdd(&g_acch[rn * 32 + lane], m);
        if (lane == 0) atomicAdd(&g_accc[rn * 3 + 0], d0 * tj);
        if (lane == 1) atomicAdd(&g_accc[rn * 3 + 1], d1 * tj);
        if (lane == 2) atomicAdd(&g_accc[rn * 3 + 2], d2 * tj);
    }
}

// -------- node update: h = relu(h + acc_h/cnt); coord += acc_c/cnt; re-zero acc ----
__global__ void k_update() {
    int idx = blockIdx.x * blockDim.x + threadIdx.x;
    if (idx >= NN * 32) return;
    int n = idx >> 5, j = idx & 31;
    float inv = g_invc[n];
    g_h[idx] = fmaxf(g_h[idx] + g_acch[idx] * inv, 0.f);
    g_acch[idx] = 0.f;
    if (j < 3) {
        g_coord[n * 3 + j] += g_accc[n * 3 + j] * inv;
        g_accc[n * 3 + j] = 0.f;
    }
}

// -------- final MLP: out = relu(h@fc2_w1+b1)@fc2_w2 + b2 (warp per node) ----------
__global__ void k_final(const float* __restrict__ w1, const float* __restrict__ b1,
                        const float* __restrict__ w2, const float* __restrict__ b2,
                        float* __restrict__ out) {
    int lane = threadIdx.x & 31;
    int n = (blockIdx.x * blockDim.x + threadIdx.x) >> 5;
    if (n >= NN) return;
    float hv = g_h[n * 32 + lane];
    float t0 = b1[lane], t1 = b1[32 + lane];
#pragma unroll
    for (int j = 0; j < 32; j++) {
        float hj = __shfl_sync(0xffffffffu, hv, j);
        t0 += hj * w1[j * 64 + lane];
        t1 += hj * w1[j * 64 + 32 + lane];
    }
    float s = fmaxf(t0, 0.f) * w2[lane] + fmaxf(t1, 0.f) * w2[32 + lane];
#pragma unroll
    for (int o = 16; o; o >>= 1) s += __shfl_xor_sync(0xffffffffu, s, o);
    if (lane == 0) out[n] = s + b2[0];
}

__global__ void k_copyc(float* __restrict__ out) {
    int idx = blockIdx.x * blockDim.x + threadIdx.x;
    if (idx < NN * 3) out[NN + idx] = g_coord[idx];
}

// ---------------------------------------------------------------------------------
extern "C" void kernel_launch(void* const* d_in, const int* in_sizes, int n_in,
                              void* d_out, int out_size) {
    const float* x    = (const float*)d_in[0];
    const int*   ei   = (const int*)d_in[1];
    const float* attr = (const float*)d_in[2];
    const float* ci   = (const float*)d_in[3];
    const float* f1w  = (const float*)d_in[4];
    const float* f1b  = (const float*)d_in[5];
    const float* kw1  = (const float*)d_in[6];
    const float* kb1  = (const float*)d_in[7];
    const float* kw2  = (const float*)d_in[8];
    const float* kb2  = (const float*)d_in[9];
    const float* kw3  = (const float*)d_in[10];
    const float* kb3  = (const float*)d_in[11];
    const float* cw1  = (const float*)d_in[12];
    const float* cb1  = (const float*)d_in[13];
    const float* cw2  = (const float*)d_in[14];
    const float* f2w1 = (const float*)d_in[15];
    const float* f2b1 = (const float*)d_in[16];
    const float* f2w2 = (const float*)d_in[17];
    const float* f2b2 = (const float*)d_in[18];
    float* out = (float*)d_out;

    k_prep<<<(NN * 32 + 255) / 256, 256>>>(x, f1w, f1b, ci);
    k_hist<<<(EE + 255) / 256, 256>>>(ei);
    k_scan<<<1, 1024>>>();
    k_invc<<<(NN + 255) / 256, 256>>>();
    k_scatter<<<(EE + 255) / 256, 256>>>(ei);

    for (int L = 0; L < 3; L++) {
        k_edge_mlp<<<(EE + 63) / 64, 256>>>(ei, attr, kw1, kb1, kw2, kb2);
        k_w3h<<<dim3(32, (NN + 31) / 32), 256>>>(kw3);
        k_contract<<<(NN + 3) / 4, 128>>>(ei, kb3, cw1, cb1, cw2);
        k_update<<<(NN * 32 + 255) / 256, 256>>>();
    }

    k_final<<<(NN * 32 + 255) / 256, 256>>>(f2w1, f2b1, f2w2, f2b2, out);
    k_copyc<<<(NN * 3 + 255) / 256, 256>>>(out);
}

// round 2
// speedup vs baseline: 1.2829x; 1.2829x over previous
#include <cuda_runtime.h>

#define NN 10000
#define EE 100000

// ---------------- scratch (static device globals; no allocation) ----------------
__device__ float g_h[NN * 32];
__device__ float g_coord[NN * 3];
__device__ float g_k2[(size_t)EE * 128];
__device__ float g_W3h[(size_t)NN * 4096];
__device__ float g_acch[NN * 32];
__device__ float g_accc[NN * 3];
__device__ float g_invc[NN];
__device__ int   g_cntc[NN];
__device__ int   g_cntr[NN];
__device__ int   g_fill[NN];
__device__ int   g_cptr[NN + 1];
__device__ int   g_ebc[EE];

// ---------------- init: h = x@fc1 + b, coord copy, zero accumulators/counters ----
__global__ void k_prep(const float* __restrict__ x, const float* __restrict__ w,
                       const float* __restrict__ b, const float* __restrict__ ci) {
    int idx = blockIdx.x * blockDim.x + threadIdx.x;
    if (idx < NN * 32) {
        int n = idx >> 5, j = idx & 31;
        float s = b[j];
        s += x[n * 3 + 0] * w[j] + x[n * 3 + 1] * w[32 + j] + x[n * 3 + 2] * w[64 + j];
        g_h[idx] = s;
        g_acch[idx] = 0.f;
    }
    if (idx < NN * 3) { g_coord[idx] = ci[idx]; g_accc[idx] = 0.f; }
    if (idx < NN) { g_cntc[idx] = 0; g_cntr[idx] = 0; g_fill[idx] = 0; }
}

__global__ void k_hist(const int* __restrict__ ei) {
    int e = blockIdx.x * blockDim.x + threadIdx.x;
    if (e < EE) {
        atomicAdd(&g_cntr[ei[e]], 1);        // row = seg_mean denominator
        atomicAdd(&g_cntc[ei[EE + e]], 1);   // col = grouping key
    }
}

// single-block exclusive scan of g_cntc -> g_cptr
__global__ void k_scan() {
    __shared__ int ss[1024];
    int t = threadIdx.x;
    int base = t * 10;
    int loc[10];
    int s = 0;
#pragma unroll
    for (int i = 0; i < 10; i++) {
        int v = (base + i < NN) ? g_cntc[base + i] : 0;
        loc[i] = s; s += v;
    }
    ss[t] = s;
    __syncthreads();
    for (int off = 1; off < 1024; off <<= 1) {
        int v = (t >= off) ? ss[t - off] : 0;
        __syncthreads();
        ss[t] += v;
        __syncthreads();
    }
    int pre = (t > 0) ? ss[t - 1] : 0;
#pragma unroll
    for (int i = 0; i < 10; i++)
        if (base + i < NN) g_cptr[base + i] = pre + loc[i];
    if (t == 1023) g_cptr[NN] = ss[1023];
}

__global__ void k_invc() {
    int n = blockIdx.x * blockDim.x + threadIdx.x;
    if (n < NN) {
        int c = g_cntr[n];
        g_invc[n] = 1.f / (float)(c > 0 ? c : 1);
    }
}

__global__ void k_scatter(const int* __restrict__ ei) {
    int e = blockIdx.x * blockDim.x + threadIdx.x;
    if (e < EE) {
        int c = ei[EE + e];
        int p = g_cptr[c] + atomicAdd(&g_fill[c], 1);
        g_ebc[p] = e;
    }
}

// -------- edge MLP: kin=[attr,radial] -> relu(@W1+b1)[64] -> relu(@W2+b2)[128] ----
// 32 edges x 128 cols per block, 256 threads. Transposed smem, broadcast a-loads.
__global__ __launch_bounds__(256) void k_edge_mlp(
    const int* __restrict__ ei, const float* __restrict__ attr,
    const float* __restrict__ W1, const float* __restrict__ B1,
    const float* __restrict__ W2, const float* __restrict__ B2) {
    __shared__ float s_kin[32][9];
    __shared__ float s_k1[64][33];    // [hidden c][edge]
    __shared__ float s_w2[64][129];   // [k][out col]
    __shared__ float s_w1[7 * 64];
    __shared__ float s_b1[64];
    __shared__ float s_b2[128];
    int t = threadIdx.x;
    int e0 = blockIdx.x * 32;

    for (int i = t; i < 7 * 64; i += 256) s_w1[i] = W1[i];
    if (t < 64) s_b1[t] = B1[t];
    else if (t < 192) s_b2[t - 64] = B2[t - 64];
    for (int i = t; i < 64 * 128; i += 256) s_w2[i >> 7][i & 127] = W2[i];

    if (t < 32) {
        int e = e0 + t;
        float rad = 0.f;
        if (e < EE) {
            int r = ei[e], c = ei[EE + e];
            float d0 = g_coord[r * 3 + 0] - g_coord[c * 3 + 0];
            float d1 = g_coord[r * 3 + 1] - g_coord[c * 3 + 1];
            float d2 = g_coord[r * 3 + 2] - g_coord[c * 3 + 2];
            rad = d0 * d0 + d1 * d1 + d2 * d2;
#pragma unroll
            for (int q = 0; q < 6; q++) s_kin[t][q] = attr[e * 6 + q];
        } else {
#pragma unroll
            for (int q = 0; q < 6; q++) s_kin[t][q] = 0.f;
        }
        s_kin[t][6] = rad;
        s_kin[t][7] = 0.f;
        s_kin[t][8] = 0.f;
    }
    __syncthreads();

    // phase 1: k1[c][e] (transposed write, conflict-free)
    for (int i = t; i < 64 * 32; i += 256) {
        int c = i >> 5, e = i & 31;
        float s = s_b1[c];
#pragma unroll
        for (int q = 0; q < 7; q++) s = fmaf(s_kin[e][q], s_w1[q * 64 + c], s);
        s_k1[c][e] = fmaxf(s, 0.f);
    }
    __syncthreads();

    // phase 2: 4 edges x 4 cols per thread; a-loads broadcast, b-loads conflict-free
    int tx = t & 31, ey = t >> 5;  // edges ey*4+i, cols tx+32*j
    float acc[4][4];
#pragma unroll
    for (int i = 0; i < 4; i++)
#pragma unroll
        for (int j = 0; j < 4; j++) acc[i][j] = 0.f;

#pragma unroll
    for (int k = 0; k < 64; k++) {
        float a[4], b[4];
#pragma unroll
        for (int i = 0; i < 4; i++) a[i] = s_k1[k][ey * 4 + i];
#pragma unroll
        for (int j = 0; j < 4; j++) b[j] = s_w2[k][tx + 32 * j];
#pragma unroll
        for (int i = 0; i < 4; i++)
#pragma unroll
            for (int j = 0; j < 4; j++) acc[i][j] = fmaf(a[i], b[j], acc[i][j]);
    }
#pragma unroll
    for (int i = 0; i < 4; i++) {
        int e = e0 + ey * 4 + i;
        if (e < EE) {
#pragma unroll
            for (int j = 0; j < 4; j++)
                g_k2[(size_t)e * 128 + tx + 32 * j] =
                    fmaxf(acc[i][j] + s_b2[tx + 32 * j], 0.f);
        }
    }
}

// -------- W3h GEMM: W3h[n][o] = sum_j h[n][j] * W3_flat[o*32+j]
// 64 nodes x 128 outs per block, 256 threads, 8n x 4o micro-tile, broadcast a-loads.
__global__ __launch_bounds__(256) void k_w3h(const float* __restrict__ W3) {
    __shared__ float s_h[32][65];    // [k][node]
    __shared__ float s_b[32][129];   // [k][out]
    int t = threadIdx.x;
    int o0 = blockIdx.x * 128;
    int n0 = blockIdx.y * 64;

    for (int i = t; i < 64 * 32; i += 256) {
        int n = i >> 5, k = i & 31;
        s_h[k][n] = (n0 + n < NN) ? g_h[(n0 + n) * 32 + k] : 0.f;
    }
    for (int i = t; i < 128 * 32; i += 256) {
        int o = i >> 5, k = i & 31;
        s_b[k][o] = W3[(size_t)(o0 + o) * 32 + k];
    }
    __syncthreads();

    int tx = t & 31, wy = t >> 5;  // nodes wy*8+i, outs tx+32*j
    float acc[8][4];
#pragma unroll
    for (int i = 0; i < 8; i++)
#pragma unroll
        for (int j = 0; j < 4; j++) acc[i][j] = 0.f;

#pragma unroll
    for (int k = 0; k < 32; k++) {
        float a[8], b[4];
#pragma unroll
        for (int i = 0; i < 8; i++) a[i] = s_h[k][wy * 8 + i];   // warp-uniform broadcast
#pragma unroll
        for (int j = 0; j < 4; j++) b[j] = s_b[k][tx + 32 * j];  // conflict-free
#pragma unroll
        for (int i = 0; i < 8; i++)
#pragma unroll
            for (int j = 0; j < 4; j++) acc[i][j] = fmaf(a[i], b[j], acc[i][j]);
    }
#pragma unroll
    for (int i = 0; i < 8; i++) {
        int n = n0 + wy * 8 + i;
        if (n < NN) {
#pragma unroll
            for (int j = 0; j < 4; j++)
                g_W3h[(size_t)n * 4096 + o0 + tx + 32 * j] = acc[i][j];
        }
    }
}

// -------- contraction: warp per (col) node. W3h[n] in 128 regs/lane.
// k2 row staged via smem double-buffer (1 coalesced LDG.128/lane prefetch);
// 4 m-accumulators break the FFMA chain; cw1 in shared to cut reg pressure.
__global__ __launch_bounds__(128, 3) void k_contract(
    const int* __restrict__ ei, const float* __restrict__ B3,
    const float* __restrict__ CW1, const float* __restrict__ CB1,
    const float* __restrict__ CW2) {
    __shared__ float  s_cw1[32][32];
    __shared__ float4 s_k2[4][2][32];
    int t = threadIdx.x, lane = t & 31, w = t >> 5;
    for (int i = t; i < 1024; i += 128) ((float*)s_cw1)[i] = CW1[i];
    __syncthreads();

    int n = blockIdx.x * 4 + w;
    if (n >= NN) return;
    int beg = g_cptr[n], end = g_cptr[n + 1];
    if (beg == end) return;

    float r[128];
    const float* wp = g_W3h + (size_t)n * 4096 + lane;
#pragma unroll
    for (int c = 0; c < 128; c++) r[c] = wp[c * 32];

    float hv = g_h[n * 32 + lane];
    float bh = 0.f;
#pragma unroll
    for (int j = 0; j < 32; j++)
        bh = fmaf(B3[lane * 32 + j], __shfl_sync(0xffffffffu, hv, j), bh);

    float cc = (lane < 3) ? g_coord[n * 3 + lane] : 0.f;
    float cb1l = CB1[lane], cw2l = CW2[lane];

    int e = g_ebc[beg];
    float4 kq = *(const float4*)(g_k2 + (size_t)e * 128 + lane * 4);
    for (int p = beg; p < end; p++) {
        int buf = p & 1;
        s_k2[w][buf][lane] = kq;
        int ecur = e;
        __syncwarp();
        if (p + 1 < end) {                       // prefetch next edge's k2 row
            e = g_ebc[p + 1];
            kq = *(const float4*)(g_k2 + (size_t)e * 128 + lane * 4);
        }
        int rn = ei[ecur];
        float m0 = bh, m1 = 0.f, m2 = 0.f, m3 = 0.f;
#pragma unroll
        for (int c = 0; c < 32; c++) {
            float4 kv = s_k2[w][buf][c];         // uniform broadcast LDS.128
            m0 = fmaf(kv.x, r[4 * c + 0], m0);
            m1 = fmaf(kv.y, r[4 * c + 1], m1);
            m2 = fmaf(kv.z, r[4 * c + 2], m2);
            m3 = fmaf(kv.w, r[4 * c + 3], m3);
        }
        float m = (m0 + m1) + (m2 + m3);

        float tj = cb1l;
#pragma unroll
        for (int i = 0; i < 32; i++)
            tj = fmaf(__shfl_sync(0xffffffffu, m, i), s_cw1[i][lane], tj);
        tj = fmaxf(tj, 0.f) * cw2l;
#pragma unroll
        for (int o = 16; o; o >>= 1) tj += __shfl_xor_sync(0xffffffffu, tj, o);

        atomicAdd(&g_acch[rn * 32 + lane], m);
        if (lane < 3)
            atomicAdd(&g_accc[rn * 3 + lane], (g_coord[rn * 3 + lane] - cc) * tj);
    }
}

// -------- node update: h = relu(h + acc_h/cnt); coord += acc_c/cnt; re-zero acc ----
__global__ void k_update() {
    int idx = blockIdx.x * blockDim.x + threadIdx.x;
    if (idx >= NN * 32) return;
    int n = idx >> 5, j = idx & 31;
    float inv = g_invc[n];
    g_h[idx] = fmaxf(g_h[idx] + g_acch[idx] * inv, 0.f);
    g_acch[idx] = 0.f;
    if (j < 3) {
        g_coord[n * 3 + j] += g_accc[n * 3 + j] * inv;
        g_accc[n * 3 + j] = 0.f;
    }
}

// -------- final MLP: out = relu(h@fc2_w1+b1)@fc2_w2 + b2 (warp per node) ----------
__global__ void k_final(const float* __restrict__ w1, const float* __restrict__ b1,
                        const float* __restrict__ w2, const float* __restrict__ b2,
                        float* __restrict__ out) {
    int lane = threadIdx.x & 31;
    int n = (blockIdx.x * blockDim.x + threadIdx.x) >> 5;
    if (n >= NN) return;
    float hv = g_h[n * 32 + lane];
    float t0 = b1[lane], t1 = b1[32 + lane];
#pragma unroll
    for (int j = 0; j < 32; j++) {
        float hj = __shfl_sync(0xffffffffu, hv, j);
        t0 = fmaf(hj, w1[j * 64 + lane], t0);
        t1 = fmaf(hj, w1[j * 64 + 32 + lane], t1);
    }
    float s = fmaxf(t0, 0.f) * w2[lane] + fmaxf(t1, 0.f) * w2[32 + lane];
#pragma unroll
    for (int o = 16; o; o >>= 1) s += __shfl_xor_sync(0xffffffffu, s, o);
    if (lane == 0) out[n] = s + b2[0];
}

__global__ void k_copyc(float* __restrict__ out) {
    int idx = blockIdx.x * blockDim.x + threadIdx.x;
    if (idx < NN * 3) out[NN + idx] = g_coord[idx];
}

// ---------------------------------------------------------------------------------
extern "C" void kernel_launch(void* const* d_in, const int* in_sizes, int n_in,
                              void* d_out, int out_size) {
    const float* x    = (const float*)d_in[0];
    const int*   ei   = (const int*)d_in[1];
    const float* attr = (const float*)d_in[2];
    const float* ci   = (const float*)d_in[3];
    const float* f1w  = (const float*)d_in[4];
    const float* f1b  = (const float*)d_in[5];
    const float* kw1  = (const float*)d_in[6];
    const float* kb1  = (const float*)d_in[7];
    const float* kw2  = (const float*)d_in[8];
    const float* kb2  = (const float*)d_in[9];
    const float* kw3  = (const float*)d_in[10];
    const float* kb3  = (const float*)d_in[11];
    const float* cw1  = (const float*)d_in[12];
    const float* cb1  = (const float*)d_in[13];
    const float* cw2  = (const float*)d_in[14];
    const float* f2w1 = (const float*)d_in[15];
    const float* f2b1 = (const float*)d_in[16];
    const float* f2w2 = (const float*)d_in[17];
    const float* f2b2 = (const float*)d_in[18];
    float* out = (float*)d_out;

    dim3 w3h_grid(32, (NN + 63) / 64);

    k_prep<<<(NN * 32 + 255) / 256, 256>>>(x, f1w, f1b, ci);
    k_hist<<<(EE + 255) / 256, 256>>>(ei);
    k_scan<<<1, 1024>>>();
    k_w3h<<<w3h_grid, 256>>>(kw3);              // layer 0 W3h (profiled slot)
    k_invc<<<(NN + 255) / 256, 256>>>();
    k_scatter<<<(EE + 255) / 256, 256>>>(ei);

    // layer 0
    k_edge_mlp<<<(EE + 31) / 32, 256>>>(ei, attr, kw1, kb1, kw2, kb2);
    k_contract<<<(NN + 3) / 4, 128>>>(ei, kb3, cw1, cb1, cw2);
    k_update<<<(NN * 32 + 255) / 256, 256>>>();

    // layers 1,2
    for (int L = 1; L < 3; L++) {
        k_edge_mlp<<<(EE + 31) / 32, 256>>>(ei, attr, kw1, kb1, kw2, kb2);
        k_w3h<<<w3h_grid, 256>>>(kw3);
        k_contract<<<(NN + 3) / 4, 128>>>(ei, kb3, cw1, cb1, cw2);
        k_update<<<(NN * 32 + 255) / 256, 256>>>();
    }

    k_final<<<(NN * 32 + 255) / 256, 256>>>(f2w1, f2b1, f2w2, f2b2, out);
    k_copyc<<<(NN * 3 + 255) / 256, 256>>>(out);
}

// round 3
// speedup vs baseline: 1.5720x; 1.2254x over previous
#include <cuda_runtime.h>

#define NN 10000
#define EE 100000

// ---------------- scratch (static device globals; no allocation) ----------------
__device__ float g_h[NN * 32];
__device__ float g_coord[NN * 3];
__device__ float g_k2[(size_t)EE * 128];
__device__ float g_W3h[(size_t)NN * 4096];
__device__ float g_acch[NN * 32];
__device__ float g_accc[NN * 3];
__device__ float g_invc[NN];
__device__ int   g_cntc[NN];
__device__ int   g_cntr[NN];
__device__ int   g_fill[NN];
__device__ int   g_cptr[NN + 1];
__device__ int   g_ebc[EE];

__device__ __forceinline__ unsigned f2tf32(float f) {
    unsigned u;
    asm("cvt.rna.tf32.f32 %0, %1;" : "=r"(u) : "f"(f));
    return u;
}

__device__ __forceinline__ void mma_tf32(float& c0, float& c1, float& c2, float& c3,
                                         unsigned a0, unsigned a1, unsigned a2, unsigned a3,
                                         unsigned b0, unsigned b1) {
    asm("mma.sync.aligned.m16n8k8.row.col.f32.tf32.tf32.f32 "
        "{%0,%1,%2,%3}, {%4,%5,%6,%7}, {%8,%9}, {%0,%1,%2,%3};"
        : "+f"(c0), "+f"(c1), "+f"(c2), "+f"(c3)
        : "r"(a0), "r"(a1), "r"(a2), "r"(a3), "r"(b0), "r"(b1));
}

// ---------------- init: h = x@fc1 + b, coord copy, zero accumulators/counters ----
__global__ void k_prep(const float* __restrict__ x, const float* __restrict__ w,
                       const float* __restrict__ b, const float* __restrict__ ci) {
    int idx = blockIdx.x * blockDim.x + threadIdx.x;
    if (idx < NN * 32) {
        int n = idx >> 5, j = idx & 31;
        float s = b[j];
        s += x[n * 3 + 0] * w[j] + x[n * 3 + 1] * w[32 + j] + x[n * 3 + 2] * w[64 + j];
        g_h[idx] = s;
        g_acch[idx] = 0.f;
    }
    if (idx < NN * 3) { g_coord[idx] = ci[idx]; g_accc[idx] = 0.f; }
    if (idx < NN) { g_cntc[idx] = 0; g_cntr[idx] = 0; g_fill[idx] = 0; }
}

__global__ void k_hist(const int* __restrict__ ei) {
    int e = blockIdx.x * blockDim.x + threadIdx.x;
    if (e < EE) {
        atomicAdd(&g_cntr[ei[e]], 1);        // row = seg_mean denominator
        atomicAdd(&g_cntc[ei[EE + e]], 1);   // col = grouping key
    }
}

// single-block exclusive scan of g_cntc -> g_cptr
__global__ void k_scan() {
    __shared__ int ss[1024];
    int t = threadIdx.x;
    int base = t * 10;
    int loc[10];
    int s = 0;
#pragma unroll
    for (int i = 0; i < 10; i++) {
        int v = (base + i < NN) ? g_cntc[base + i] : 0;
        loc[i] = s; s += v;
    }
    ss[t] = s;
    __syncthreads();
    for (int off = 1; off < 1024; off <<= 1) {
        int v = (t >= off) ? ss[t - off] : 0;
        __syncthreads();
        ss[t] += v;
        __syncthreads();
    }
    int pre = (t > 0) ? ss[t - 1] : 0;
#pragma unroll
    for (int i = 0; i < 10; i++)
        if (base + i < NN) g_cptr[base + i] = pre + loc[i];
    if (t == 1023) g_cptr[NN] = ss[1023];
}

__global__ void k_invc() {
    int n = blockIdx.x * blockDim.x + threadIdx.x;
    if (n < NN) {
        int c = g_cntr[n];
        g_invc[n] = 1.f / (float)(c > 0 ? c : 1);
    }
}

__global__ void k_scatter(const int* __restrict__ ei) {
    int e = blockIdx.x * blockDim.x + threadIdx.x;
    if (e < EE) {
        int c = ei[EE + e];
        int p = g_cptr[c] + atomicAdd(&g_fill[c], 1);
        g_ebc[p] = e;
    }
}

// -------- edge MLP: kin=[attr,radial] -> relu(@W1+b1)[64] -> relu(@W2+b2)[128] ----
// 32 edges x 128 cols per block, 256 threads. float4 LDS/STG in phase 2.
__global__ __launch_bounds__(256) void k_edge_mlp(
    const int* __restrict__ ei, const float* __restrict__ attr,
    const float* __restrict__ W1, const float* __restrict__ B1,
    const float* __restrict__ W2, const float* __restrict__ B2) {
    __shared__ float s_kin[32][9];
    __shared__ float s_k1[64][36];    // [hidden c][edge], pad for aligned float4
    __shared__ float s_w2[64][132];   // [k][out col], pad for aligned float4
    __shared__ float s_w1[7 * 64];
    __shared__ float s_b1[64];
    __shared__ float s_b2[128];
    int t = threadIdx.x;
    int e0 = blockIdx.x * 32;

    for (int i = t; i < 7 * 64; i += 256) s_w1[i] = W1[i];
    if (t < 64) s_b1[t] = B1[t];
    else if (t < 192) s_b2[t - 64] = B2[t - 64];
    for (int i = t; i < 64 * 32; i += 256) {
        int k = i >> 5, q = i & 31;
        *(float4*)&s_w2[k][q * 4] = *(const float4*)&W2[k * 128 + q * 4];
    }

    if (t < 32) {
        int e = e0 + t;
        float rad = 0.f;
        if (e < EE) {
            int r = ei[e], c = ei[EE + e];
            float d0 = g_coord[r * 3 + 0] - g_coord[c * 3 + 0];
            float d1 = g_coord[r * 3 + 1] - g_coord[c * 3 + 1];
            float d2 = g_coord[r * 3 + 2] - g_coord[c * 3 + 2];
            rad = d0 * d0 + d1 * d1 + d2 * d2;
#pragma unroll
            for (int q = 0; q < 6; q++) s_kin[t][q] = attr[e * 6 + q];
        } else {
#pragma unroll
            for (int q = 0; q < 6; q++) s_kin[t][q] = 0.f;
        }
        s_kin[t][6] = rad;
        s_kin[t][7] = 0.f;
        s_kin[t][8] = 0.f;
    }
    __syncthreads();

    // phase 1: k1[c][e] (transposed write)
    for (int i = t; i < 64 * 32; i += 256) {
        int c = i >> 5, e = i & 31;
        float s = s_b1[c];
#pragma unroll
        for (int q = 0; q < 7; q++) s = fmaf(s_kin[e][q], s_w1[q * 64 + c], s);
        s_k1[c][e] = fmaxf(s, 0.f);
    }
    __syncthreads();

    // phase 2: 4 edges x 4 contiguous cols per thread; 2 x LDS.128 per k-step
    int tx = t & 31, ey = t >> 5;  // edges ey*4+i, cols 4*tx+j
    float acc[4][4];
#pragma unroll
    for (int i = 0; i < 4; i++)
#pragma unroll
        for (int j = 0; j < 4; j++) acc[i][j] = 0.f;

#pragma unroll
    for (int k = 0; k < 64; k++) {
        float4 av = *(const float4*)&s_k1[k][ey * 4];   // broadcast
        float4 bv = *(const float4*)&s_w2[k][tx * 4];   // conflict-free
        float a[4] = {av.x, av.y, av.z, av.w};
        float b[4] = {bv.x, bv.y, bv.z, bv.w};
#pragma unroll
        for (int i = 0; i < 4; i++)
#pragma unroll
            for (int j = 0; j < 4; j++) acc[i][j] = fmaf(a[i], b[j], acc[i][j]);
    }
    float4 b2v = *(const float4*)&s_b2[tx * 4];
#pragma unroll
    for (int i = 0; i < 4; i++) {
        int e = e0 + ey * 4 + i;
        if (e < EE) {
            float4 r;
            r.x = fmaxf(acc[i][0] + b2v.x, 0.f);
            r.y = fmaxf(acc[i][1] + b2v.y, 0.f);
            r.z = fmaxf(acc[i][2] + b2v.z, 0.f);
            r.w = fmaxf(acc[i][3] + b2v.w, 0.f);
            *(float4*)&g_k2[(size_t)e * 128 + tx * 4] = r;
        }
    }
}

// -------- W3h GEMM via tf32 mma: W3h[n][o] = sum_j h[n][j] * W3[o*32+j]
// Block tile 64 nodes x 256 outs, K=32. 8 warps: 4 m-warps x 2 n-warps,
// warp tile 16n x 128o = 16 mma n-tiles x 4 k-steps.
__global__ __launch_bounds__(256) void k_w3h_mma(const float* __restrict__ W3) {
    __shared__ unsigned s_a[64][36];    // [node][k] tf32, pad 36 -> 4r+c banks
    __shared__ unsigned s_b[256][36];   // [o][k]    tf32 (W3 row o is col-major k x n)
    int t = threadIdx.x, warp = t >> 5, lane = t & 31;
    int o0 = blockIdx.x * 256, n0 = blockIdx.y * 64;

    // stage A: 64 x 32
    for (int i = t; i < 64 * 8; i += 256) {
        int n = i >> 3, kq = i & 7;
        float4 v = make_float4(0.f, 0.f, 0.f, 0.f);
        if (n0 + n < NN) v = *(const float4*)&g_h[(n0 + n) * 32 + kq * 4];
        s_a[n][kq * 4 + 0] = f2tf32(v.x);
        s_a[n][kq * 4 + 1] = f2tf32(v.y);
        s_a[n][kq * 4 + 2] = f2tf32(v.z);
        s_a[n][kq * 4 + 3] = f2tf32(v.w);
    }
    // stage B: 256 x 32
    for (int i = t; i < 256 * 8; i += 256) {
        int o = i >> 3, kq = i & 7;
        float4 v = *(const float4*)&W3[(size_t)(o0 + o) * 32 + kq * 4];
        s_b[o][kq * 4 + 0] = f2tf32(v.x);
        s_b[o][kq * 4 + 1] = f2tf32(v.y);
        s_b[o][kq * 4 + 2] = f2tf32(v.z);
        s_b[o][kq * 4 + 3] = f2tf32(v.w);
    }
    __syncthreads();

    int wm = warp & 3, wn = warp >> 2;
    int qr = lane >> 2, qc = lane & 3;
    float acc[16][4];
#pragma unroll
    for (int nt = 0; nt < 16; nt++)
#pragma unroll
        for (int j = 0; j < 4; j++) acc[nt][j] = 0.f;

#pragma unroll
    for (int ks = 0; ks < 4; ks++) {
        int k0 = ks * 8;
        unsigned a0 = s_a[wm * 16 + qr][k0 + qc];
        unsigned a1 = s_a[wm * 16 + qr + 8][k0 + qc];
        unsigned a2 = s_a[wm * 16 + qr][k0 + qc + 4];
        unsigned a3 = s_a[wm * 16 + qr + 8][k0 + qc + 4];
#pragma unroll
        for (int nt = 0; nt < 16; nt++) {
            int ob = wn * 128 + nt * 8;
            unsigned b0 = s_b[ob + qr][k0 + qc];
            unsigned b1 = s_b[ob + qr][k0 + qc + 4];
            mma_tf32(acc[nt][0], acc[nt][1], acc[nt][2], acc[nt][3],
                     a0, a1, a2, a3, b0, b1);
        }
    }

    int nA = n0 + wm * 16 + qr;
    int nB = nA + 8;
#pragma unroll
    for (int nt = 0; nt < 16; nt++) {
        int o = o0 + wn * 128 + nt * 8 + 2 * qc;
        if (nA < NN) *(float2*)&g_W3h[(size_t)nA * 4096 + o] = make_float2(acc[nt][0], acc[nt][1]);
        if (nB < NN) *(float2*)&g_W3h[(size_t)nB * 4096 + o] = make_float2(acc[nt][2], acc[nt][3]);
    }
}

// -------- contraction: warp per (col) node. W3h[n] in 128 regs/lane. ----------
__global__ __launch_bounds__(128, 3) void k_contract(
    const int* __restrict__ ei, const float* __restrict__ B3,
    const float* __restrict__ CW1, const float* __restrict__ CB1,
    const float* __restrict__ CW2) {
    __shared__ float  s_cw1[32][32];
    __shared__ float4 s_k2[4][2][32];
    int t = threadIdx.x, lane = t & 31, w = t >> 5;
    for (int i = t; i < 1024; i += 128) ((float*)s_cw1)[i] = CW1[i];
    __syncthreads();

    int n = blockIdx.x * 4 + w;
    if (n >= NN) return;
    int beg = g_cptr[n], end = g_cptr[n + 1];
    if (beg == end) return;

    float r[128];
    const float* wp = g_W3h + (size_t)n * 4096 + lane;
#pragma unroll
    for (int c = 0; c < 128; c++) r[c] = wp[c * 32];

    float hv = g_h[n * 32 + lane];
    float bh = 0.f;
#pragma unroll
    for (int j = 0; j < 32; j++)
        bh = fmaf(B3[lane * 32 + j], __shfl_sync(0xffffffffu, hv, j), bh);

    float cc = (lane < 3) ? g_coord[n * 3 + lane] : 0.f;
    float cb1l = CB1[lane], cw2l = CW2[lane];

    int e = g_ebc[beg];
    float4 kq = *(const float4*)(g_k2 + (size_t)e * 128 + lane * 4);
    for (int p = beg; p < end; p++) {
        int buf = p & 1;
        s_k2[w][buf][lane] = kq;
        int ecur = e;
        __syncwarp();
        if (p + 1 < end) {
            e = g_ebc[p + 1];
            kq = *(const float4*)(g_k2 + (size_t)e * 128 + lane * 4);
        }
        int rn = ei[ecur];
        float m0 = bh, m1 = 0.f, m2 = 0.f, m3 = 0.f;
#pragma unroll
        for (int c = 0; c < 32; c++) {
            float4 kv = s_k2[w][buf][c];
            m0 = fmaf(kv.x, r[4 * c + 0], m0);
            m1 = fmaf(kv.y, r[4 * c + 1], m1);
            m2 = fmaf(kv.z, r[4 * c + 2], m2);
            m3 = fmaf(kv.w, r[4 * c + 3], m3);
        }
        float m = (m0 + m1) + (m2 + m3);

        float tj = cb1l;
#pragma unroll
        for (int i = 0; i < 32; i++)
            tj = fmaf(__shfl_sync(0xffffffffu, m, i), s_cw1[i][lane], tj);
        tj = fmaxf(tj, 0.f) * cw2l;
#pragma unroll
        for (int o = 16; o; o >>= 1) tj += __shfl_xor_sync(0xffffffffu, tj, o);

        atomicAdd(&g_acch[rn * 32 + lane], m);
        if (lane < 3)
            atomicAdd(&g_accc[rn * 3 + lane], (g_coord[rn * 3 + lane] - cc) * tj);
    }
}

// -------- node update: h = relu(h + acc_h/cnt); coord += acc_c/cnt; re-zero acc ----
__global__ void k_update() {
    int idx = blockIdx.x * blockDim.x + threadIdx.x;
    if (idx >= NN * 32) return;
    int n = idx >> 5, j = idx & 31;
    float inv = g_invc[n];
    g_h[idx] = fmaxf(g_h[idx] + g_acch[idx] * inv, 0.f);
    g_acch[idx] = 0.f;
    if (j < 3) {
        g_coord[n * 3 + j] += g_accc[n * 3 + j] * inv;
        g_accc[n * 3 + j] = 0.f;
    }
}

// -------- final MLP (warp per node) + coord copy ----------------------------------
__global__ void k_final(const float* __restrict__ w1, const float* __restrict__ b1,
                        const float* __restrict__ w2, const float* __restrict__ b2,
                        float* __restrict__ out) {
    int gid = blockIdx.x * blockDim.x + threadIdx.x;
    if (gid < NN * 3) out[NN + gid] = g_coord[gid];
    int lane = gid & 31;
    int n = gid >> 5;
    if (n >= NN) return;
    float hv = g_h[n * 32 + lane];
    float t0 = b1[lane], t1 = b1[32 + lane];
#pragma unroll
    for (int j = 0; j < 32; j++) {
        float hj = __shfl_sync(0xffffffffu, hv, j);
        t0 = fmaf(hj, w1[j * 64 + lane], t0);
        t1 = fmaf(hj, w1[j * 64 + 32 + lane], t1);
    }
    float s = fmaxf(t0, 0.f) * w2[lane] + fmaxf(t1, 0.f) * w2[32 + lane];
#pragma unroll
    for (int o = 16; o; o >>= 1) s += __shfl_xor_sync(0xffffffffu, s, o);
    if (lane == 0) out[n] = s + b2[0];
}

// ---------------------------------------------------------------------------------
extern "C" void kernel_launch(void* const* d_in, const int* in_sizes, int n_in,
                              void* d_out, int out_size) {
    const float* x    = (const float*)d_in[0];
    const int*   ei   = (const int*)d_in[1];
    const float* attr = (const float*)d_in[2];
    const float* ci   = (const float*)d_in[3];
    const float* f1w  = (const float*)d_in[4];
    const float* f1b  = (const float*)d_in[5];
    const float* kw1  = (const float*)d_in[6];
    const float* kb1  = (const float*)d_in[7];
    const float* kw2  = (const float*)d_in[8];
    const float* kb2  = (const float*)d_in[9];
    const float* kw3  = (const float*)d_in[10];
    const float* kb3  = (const float*)d_in[11];
    const float* cw1  = (const float*)d_in[12];
    const float* cb1  = (const float*)d_in[13];
    const float* cw2  = (const float*)d_in[14];
    const float* f2w1 = (const float*)d_in[15];
    const float* f2b1 = (const float*)d_in[16];
    const float* f2w2 = (const float*)d_in[17];
    const float* f2b2 = (const float*)d_in[18];
    float* out = (float*)d_out;

    dim3 w3h_grid(4096 / 256, (NN + 63) / 64);

    k_prep<<<(NN * 32 + 255) / 256, 256>>>(x, f1w, f1b, ci);
    k_hist<<<(EE + 255) / 256, 256>>>(ei);
    k_scan<<<1, 1024>>>();
    k_edge_mlp<<<(EE + 31) / 32, 256>>>(ei, attr, kw1, kb1, kw2, kb2);  // profiled slot
    k_invc<<<(NN + 255) / 256, 256>>>();
    k_scatter<<<(EE + 255) / 256, 256>>>(ei);

    // layer 0 (edge_mlp already done)
    k_w3h_mma<<<w3h_grid, 256>>>(kw3);
    k_contract<<<(NN + 3) / 4, 128>>>(ei, kb3, cw1, cb1, cw2);
    k_update<<<(NN * 32 + 255) / 256, 256>>>();

    // layers 1,2
    for (int L = 1; L < 3; L++) {
        k_edge_mlp<<<(EE + 31) / 32, 256>>>(ei, attr, kw1, kb1, kw2, kb2);
        k_w3h_mma<<<w3h_grid, 256>>>(kw3);
        k_contract<<<(NN + 3) / 4, 128>>>(ei, kb3, cw1, cb1, cw2);
        k_update<<<(NN * 32 + 255) / 256, 256>>>();
    }

    k_final<<<(NN * 32 + 255) / 256, 256>>>(f2w1, f2b1, f2w2, f2b2, out);
}